// round 8
// baseline (speedup 1.0000x reference)
#include <cuda_runtime.h>
#include <cuda_bf16.h>
#include <cstdint>

// Problem shape (fixed for this problem id)
#define BB   16
#define SS   768
#define DE   16
#define HID  128
#define BSN  (BB*SS)          // 12288 rows
#define ROWF (SS*DE)          // 12288 floats per (b,i) row
#define ROWF4 (ROWF/4)        // 3072 float4 per row

#define NB_NODE (BSN/8)       // 1536 nodedot blocks (8 rows each)
#define NB_MASK 24            // mask canonicalize blocks
#define NB_PREP (NB_NODE + NB_MASK + 1)

// ---- scratch (no allocations allowed) ----
__device__ float g_edge_sum[BSN];
__device__ float g_dist[BSN];
__device__ float g_nodeacc[BSN];     // node_row . (W_node @ W_imp[:32])
__device__ float g_v[64];
__device__ float g_C[1];
__device__ unsigned char g_mask[BSN];

// ============================================================================
// Kernel 1: prep — 1561 independent blocks, 256 threads.
//   blk < 1536      : nodedot — fold w_nc locally, dot 8 node rows (1 warp/row)
//   1536 <= blk<1560: dtype-detect + canonicalize a 512-elem mask slice
//   blk == 1560     : fold v = W_e2 @ W_imp[32:],  C = bias fold
// ============================================================================
__global__ void __launch_bounds__(256) prep_kernel(
                            const void* __restrict__ pocket_raw,
                            const float* __restrict__ node,
                            const float* __restrict__ W_node,
                            const float* __restrict__ b_node,
                            const float* __restrict__ W_e2,
                            const float* __restrict__ b_e2,
                            const float* __restrict__ W_imp,
                            const float* __restrict__ b_imp)
{
    const int blk = blockIdx.x;
    const int t = threadIdx.x;

    if (blk < NB_NODE) {
        // ---- nodedot: fold w_nc into smem, then 8 warp-per-row dots ----
        __shared__ float swnc[HID];
        if (t < HID) {
            float s = 0.0f;
            #pragma unroll
            for (int k = 0; k < 32; k++) s += W_node[t * 32 + k] * W_imp[k];
            swnc[t] = s;
        }
        __syncthreads();

        const int w = t >> 5, l = t & 31;
        const int row = blk * 8 + w;
        const float4 nv = __ldg((const float4*)(node + (size_t)row * HID) + l);
        float acc = nv.x * swnc[l * 4 + 0] + nv.y * swnc[l * 4 + 1]
                  + nv.z * swnc[l * 4 + 2] + nv.w * swnc[l * 4 + 3];
        #pragma unroll
        for (int o = 16; o; o >>= 1) acc += __shfl_xor_sync(0xFFFFFFFFu, acc, o);
        if (l == 0) g_nodeacc[row] = acc;
    } else if (blk < NB_NODE + NB_MASK) {
        // ---- dtype scan (redundant, identical result) + slice canonicalize ----
        __shared__ int s_fone, s_other;
        if (t == 0) { s_fone = 0; s_other = 0; }
        __syncthreads();
        {
            const unsigned int* wp = (const unsigned int*)pocket_raw;
            unsigned int x[12];
            #pragma unroll
            for (int u = 0; u < 12; u++) x[u] = wp[t + u * 256];
            int lf = 0, lo = 0;
            #pragma unroll
            for (int u = 0; u < 12; u++) {
                if (x[u] == 0x3F800000u) lf++;
                else if (x[u] != 0u && x[u] != 1u) lo++;
            }
            if (lf) atomicAdd(&s_fone, lf);
            if (lo) atomicAdd(&s_other, lo);
        }
        __syncthreads();
        // mode: 0=float32 (saw 1.0f), 2=bool/u8 (packed bytes), 1=int32
        const int mode = (s_fone > 0) ? 0 : ((s_other > 0) ? 2 : 1);

        const int base = (blk - NB_NODE) * 512;
        if (mode == 0) {
            const float* p = (const float*)pocket_raw;
            #pragma unroll
            for (int u = 0; u < 2; u++) {
                const int idx = base + t + u * 256;
                g_mask[idx] = (p[idx] != 0.0f) ? 1 : 0;
            }
        } else if (mode == 1) {
            const int* p = (const int*)pocket_raw;
            #pragma unroll
            for (int u = 0; u < 2; u++) {
                const int idx = base + t + u * 256;
                g_mask[idx] = (p[idx] != 0) ? 1 : 0;
            }
        } else {
            const unsigned char* p = (const unsigned char*)pocket_raw;
            #pragma unroll
            for (int u = 0; u < 2; u++) {
                const int idx = base + t + u * 256;
                g_mask[idx] = (p[idx] != 0) ? 1 : 0;
            }
        }
    } else {
        // ---- fold v (64 outputs) + C ----
        if (t < 64) {
            float s = 0.0f;
            #pragma unroll
            for (int k = 0; k < 32; k++) s += W_e2[t * 32 + k] * W_imp[32 + k];
            g_v[t] = s;
        }
        if (t == 0) {
            float c = b_imp[0];
            #pragma unroll
            for (int k = 0; k < 32; k++) c += b_node[k] * W_imp[k];
            #pragma unroll
            for (int k = 0; k < 32; k++) c += b_e2[k] * W_imp[32 + k];
            g_C[0] = c;
        }
    }
}

// ============================================================================
// Kernel 2: edge pass — the 604 MB streaming pass (R5/R7 exact, at LTS cap).
// One block per (b,i) row: fused (sum over S*De) + (masked min over channel 0).
// ============================================================================
__global__ void __launch_bounds__(256) edge_kernel(const float* __restrict__ edge)
{
    const int i = blockIdx.x;
    const int b = blockIdx.y;
    const int t = threadIdx.x;

    __shared__ unsigned char sm[SS];
    for (int k = t; k < SS; k += 256) sm[k] = g_mask[b * SS + k];
    __syncthreads();

    const float4* __restrict__ row =
        (const float4*)(edge + ((size_t)(b * SS + i)) * (size_t)ROWF);

    const float INF = __int_as_float(0x7f800000);
    float sum0 = 0.0f, sum1 = 0.0f;
    float mn = INF;
    #pragma unroll
    for (int it = 0; it < ROWF4 / 256; it++) {
        const int k = t + it * 256;
        float4 v = __ldcs(row + k);
        if (it & 1) sum1 += (v.x + v.y) + (v.z + v.w);
        else        sum0 += (v.x + v.y) + (v.z + v.w);
        if ((k & 3) == 0) {                 // channel 0 of edge feature j
            const int j = k >> 2;
            const float cand = sm[j] ? v.x : INF;   // select, no branch
            mn = fminf(mn, cand);
        }
    }
    float sum = sum0 + sum1;

    // warp reduce
    #pragma unroll
    for (int o = 16; o; o >>= 1) {
        sum += __shfl_xor_sync(0xFFFFFFFFu, sum, o);
        mn   = fminf(mn, __shfl_xor_sync(0xFFFFFFFFu, mn, o));
    }
    __shared__ float ssum[8], smn[8];
    const int wid = t >> 5, lid = t & 31;
    if (lid == 0) { ssum[wid] = sum; smn[wid] = mn; }
    __syncthreads();
    if (t == 0) {
        float S = 0.0f, M = INF;
        #pragma unroll
        for (int k = 0; k < 8; k++) { S += ssum[k]; M = fminf(M, smn[k]); }
        g_edge_sum[b * SS + i] = S;
        g_dist[b * SS + i]     = M;
    }
}

// ============================================================================
// Kernel 3: final2 — one block per batch, 768 threads, one row per thread.
// No node loads (nodeacc precomputed); edge-MLP is a 64-FMA serial chain on
// smem broadcasts. Fixed-order reductions => deterministic across replays.
// ============================================================================
__global__ void __launch_bounds__(768) final2_kernel(const float* __restrict__ seqmask,
                                                     const float* __restrict__ We1,
                                                     const float* __restrict__ be1,
                                                     float* __restrict__ out, int out_size)
{
    const int b = blockIdx.x;
    const int t = threadIdx.x;
    const int w = t >> 5, l = t & 31;

    __shared__ float sw1[64], sb1[64], sv[64];
    __shared__ float simp[SS];
    __shared__ float wred[24];
    __shared__ int   wcnt[24], wany[24];
    __shared__ float s_mean;

    if (t < 64) { sw1[t] = We1[t]; sb1[t] = be1[t]; sv[t] = g_v[t]; }
    __syncthreads();

    // ---- per-thread importance for row t of batch b ----
    const int row = b * SS + t;
    const float es = g_edge_sum[row] * (1.0f / (float)ROWF);
    float e = 0.0f;
    #pragma unroll
    for (int j = 0; j < 64; j++)
        e += fmaxf(es * sw1[j] + sb1[j], 0.0f) * sv[j];
    const float logit = g_nodeacc[row] + e + g_C[0];
    const float imp = (1.0f / (1.0f + expf(-logit))) * seqmask[row];
    simp[t] = imp;
    __syncthreads();

    // ---- mean (768 elems, fixed order: warp shuffle + 24-partial sum) ----
    float s = simp[t];
    #pragma unroll
    for (int o = 16; o; o >>= 1) s += __shfl_xor_sync(0xFFFFFFFFu, s, o);
    if (l == 0) wred[w] = s;
    __syncthreads();
    if (t == 0) {
        float S = 0.0f;
        #pragma unroll
        for (int k = 0; k < 24; k++) S += wred[k];
        s_mean = S * (1.0f / (float)SS);
    }
    __syncthreads();
    const float mean = s_mean;

    // ---- merged count + any(pocket): one element per thread ----
    const bool p = g_mask[row] != 0;
    const float d = g_dist[row];
    const bool core  = d < 6.0f;
    const bool shell = (d >= 6.0f) && (d < 10.0f) && (imp > mean);
    int cnt  = (p | core | shell) ? 1 : 0;
    int anyp = p ? 1 : 0;
    #pragma unroll
    for (int o = 16; o; o >>= 1) {
        cnt  += __shfl_xor_sync(0xFFFFFFFFu, cnt, o);
        anyp |= __shfl_xor_sync(0xFFFFFFFFu, anyp, o);
    }
    if (l == 0) { wcnt[w] = cnt; wany[w] = anyp; }
    __syncthreads();

    if (t == 0) {
        int Ct = 0, A = 0;
        #pragma unroll
        for (int k = 0; k < 24; k++) { Ct += wcnt[k]; A |= wany[k]; }
        float chunk;
        if (A) {
            int ml = Ct; if (ml > 256) ml = 256;               // merged_len clamp
            chunk = fminf(fmaxf((float)ml, 64.0f), 256.0f);    // clamp(adj=64, 256)
        } else {
            chunk = fminf(fmaxf(64.0f * mean, 32.0f), 128.0f); // clip(64*imp, 32, 128)
        }
        out[b] = chunk;
    }
    // pad remaining outputs (MAX_SEQ_LEN) in parallel from block 0
    if (b == 0) {
        for (int k = BB + t; k < out_size; k += 768) out[k] = 256.0f;
    }
}

// ============================================================================
extern "C" void kernel_launch(void* const* d_in, const int* in_sizes, int n_in,
                              void* d_out, int out_size)
{
    const float* node    = (const float*)d_in[0];   // [16,768,128]
    const float* edge    = (const float*)d_in[1];   // [16,768,768,16]
    const float* seqmask = (const float*)d_in[2];   // [16,768]
    const void*  pocket  = d_in[3];                 // [16,768] dtype detected at runtime
    const float* W_node  = (const float*)d_in[4];
    const float* b_node  = (const float*)d_in[5];
    const float* W_e1    = (const float*)d_in[6];
    const float* b_e1    = (const float*)d_in[7];
    const float* W_e2    = (const float*)d_in[8];
    const float* b_e2    = (const float*)d_in[9];
    const float* W_imp   = (const float*)d_in[10];
    const float* b_imp   = (const float*)d_in[11];
    float* out = (float*)d_out;

    prep_kernel<<<NB_PREP, 256>>>(pocket, node, W_node, b_node, W_e2, b_e2, W_imp, b_imp);

    dim3 eg(SS, BB);
    edge_kernel<<<eg, 256>>>(edge);

    final2_kernel<<<BB, 768>>>(seqmask, W_e1, b_e1, out, out_size);
}

// round 9
// speedup vs baseline: 1.0979x; 1.0979x over previous
#include <cuda_runtime.h>
#include <cuda_bf16.h>
#include <cstdint>

// Problem shape (fixed for this problem id)
#define BB   16
#define SS   768
#define DE   16
#define HID  128
#define BSN  (BB*SS)          // 12288 rows
#define ROWF (SS*DE)          // 12288 floats per (b,i) row
#define ROWF4 (ROWF/4)        // 3072 float4 per row

// ---- scratch (no allocations allowed) ----
__device__ float g_edge_sum[BSN];
__device__ float g_dist[BSN];
__device__ float g_wnc[HID];
__device__ float g_v[64];
__device__ float g_C[1];
__device__ unsigned char g_mask[BSN];

// ============================================================================
// Kernel 1: prep — 26 independent blocks (R7 exact, proven ~2us).
//   blocks 0..23 : dtype-detect (redundant scan, identical result) +
//                  canonicalize a 512-element slice of the pocket mask
//   block 24     : fold w_nc = W_node @ W_imp[:32]  (ONCE)
//   block 25     : fold v = W_e2 @ W_imp[32:],  C = bias fold
// ============================================================================
__global__ void __launch_bounds__(128) prep_kernel(
                            const void* __restrict__ pocket_raw,
                            const float* __restrict__ W_node,
                            const float* __restrict__ b_node,
                            const float* __restrict__ W_e2,
                            const float* __restrict__ b_e2,
                            const float* __restrict__ W_imp,
                            const float* __restrict__ b_imp)
{
    const int blk = blockIdx.x;
    const int t = threadIdx.x;

    if (blk < 24) {
        __shared__ int s_fone, s_other;
        if (t == 0) { s_fone = 0; s_other = 0; }
        __syncthreads();
        {
            const unsigned int* w = (const unsigned int*)pocket_raw;
            unsigned int x[24];
            #pragma unroll
            for (int u = 0; u < 24; u++) x[u] = w[t + u * 128];
            int lf = 0, lo = 0;
            #pragma unroll
            for (int u = 0; u < 24; u++) {
                if (x[u] == 0x3F800000u) lf++;
                else if (x[u] != 0u && x[u] != 1u) lo++;
            }
            if (lf) atomicAdd(&s_fone, lf);
            if (lo) atomicAdd(&s_other, lo);
        }
        __syncthreads();
        // mode: 0=float32 (saw 1.0f words), 2=bool/u8 (packed bytes), 1=int32
        const int mode = (s_fone > 0) ? 0 : ((s_other > 0) ? 2 : 1);

        const int base = blk * 512;
        if (mode == 0) {
            const float* p = (const float*)pocket_raw;
            #pragma unroll
            for (int u = 0; u < 4; u++) {
                const int idx = base + t + u * 128;
                g_mask[idx] = (p[idx] != 0.0f) ? 1 : 0;
            }
        } else if (mode == 1) {
            const int* p = (const int*)pocket_raw;
            #pragma unroll
            for (int u = 0; u < 4; u++) {
                const int idx = base + t + u * 128;
                g_mask[idx] = (p[idx] != 0) ? 1 : 0;
            }
        } else {
            const unsigned char* p = (const unsigned char*)pocket_raw;
            #pragma unroll
            for (int u = 0; u < 4; u++) {
                const int idx = base + t + u * 128;
                g_mask[idx] = (p[idx] != 0) ? 1 : 0;
            }
        }
    } else if (blk == 24) {
        float s = 0.0f;
        #pragma unroll
        for (int k = 0; k < 32; k++) s += W_node[t * 32 + k] * W_imp[k];
        g_wnc[t] = s;
    } else {
        if (t < 64) {
            float s = 0.0f;
            #pragma unroll
            for (int k = 0; k < 32; k++) s += W_e2[t * 32 + k] * W_imp[32 + k];
            g_v[t] = s;
        }
        if (t == 0) {
            float c = b_imp[0];
            #pragma unroll
            for (int k = 0; k < 32; k++) c += b_node[k] * W_imp[k];
            #pragma unroll
            for (int k = 0; k < 32; k++) c += b_e2[k] * W_imp[32 + k];
            g_C[0] = c;
        }
    }
}

// ============================================================================
// Kernel 2: edge pass — the 604 MB streaming pass (R5/R7 exact, at LTS cap).
// One block per (b,i) row: fused (sum over S*De) + (masked min over channel 0).
// ============================================================================
__global__ void __launch_bounds__(256) edge_kernel(const float* __restrict__ edge)
{
    const int i = blockIdx.x;
    const int b = blockIdx.y;
    const int t = threadIdx.x;

    __shared__ unsigned char sm[SS];
    for (int k = t; k < SS; k += 256) sm[k] = g_mask[b * SS + k];
    __syncthreads();

    const float4* __restrict__ row =
        (const float4*)(edge + ((size_t)(b * SS + i)) * (size_t)ROWF);

    const float INF = __int_as_float(0x7f800000);
    float sum0 = 0.0f, sum1 = 0.0f;
    float mn = INF;
    #pragma unroll
    for (int it = 0; it < ROWF4 / 256; it++) {
        const int k = t + it * 256;
        float4 v = __ldcs(row + k);
        if (it & 1) sum1 += (v.x + v.y) + (v.z + v.w);
        else        sum0 += (v.x + v.y) + (v.z + v.w);
        if ((k & 3) == 0) {                 // channel 0 of edge feature j
            const int j = k >> 2;
            const float cand = sm[j] ? v.x : INF;   // select, no branch
            mn = fminf(mn, cand);
        }
    }
    float sum = sum0 + sum1;

    // warp reduce
    #pragma unroll
    for (int o = 16; o; o >>= 1) {
        sum += __shfl_xor_sync(0xFFFFFFFFu, sum, o);
        mn   = fminf(mn, __shfl_xor_sync(0xFFFFFFFFu, mn, o));
    }
    __shared__ float ssum[8], smn[8];
    const int wid = t >> 5, lid = t & 31;
    if (lid == 0) { ssum[wid] = sum; smn[wid] = mn; }
    __syncthreads();
    if (t == 0) {
        float S = 0.0f, M = INF;
        #pragma unroll
        for (int k = 0; k < 8; k++) { S += ssum[k]; M = fminf(M, smn[k]); }
        g_edge_sum[b * SS + i] = S;
        g_dist[b * SS + i]     = M;
    }
}

// ============================================================================
// Kernel 3: final2 — one block per batch, 768 threads, ONE ROW PER THREAD.
// Node dot in-kernel: each thread streams its own 512B node row (32 float4,
// unrolled x8 => high MLP); weights via smem broadcast (conflict-free).
// All thread-independent work; fixed-order reductions => deterministic.
// ============================================================================
__global__ void __launch_bounds__(768) final2_kernel(const float* __restrict__ node,
                                                     const float* __restrict__ seqmask,
                                                     const float* __restrict__ We1,
                                                     const float* __restrict__ be1,
                                                     float* __restrict__ out, int out_size)
{
    const int b = blockIdx.x;
    const int t = threadIdx.x;
    const int w = t >> 5, l = t & 31;

    __shared__ float swnc[HID], sw1[64], sb1[64], sv[64];
    __shared__ float simp[SS];
    __shared__ float wred[24];
    __shared__ int   wcnt[24], wany[24];
    __shared__ float s_mean;

    if (t < HID) swnc[t] = g_wnc[t];
    if (t < 64) { sw1[t] = We1[t]; sb1[t] = be1[t]; sv[t] = g_v[t]; }
    __syncthreads();

    const int row = b * SS + t;

    // early scalar loads (overlap with the dot below)
    const float es_raw = g_edge_sum[row];
    const float d      = g_dist[row];
    const bool  p      = g_mask[row] != 0;
    const float smask  = seqmask[row];

    // ---- per-thread node dot: 32 float4 loads, 4 passes of 8 (MLP=8) ----
    const float4* __restrict__ nr = (const float4*)(node + (size_t)row * HID);
    float acc = 0.0f;
    #pragma unroll
    for (int pass = 0; pass < 4; pass++) {
        float4 x[8];
        #pragma unroll
        for (int u = 0; u < 8; u++) x[u] = __ldg(nr + pass * 8 + u);
        #pragma unroll
        for (int u = 0; u < 8; u++) {
            const int c = (pass * 8 + u) * 4;
            acc += x[u].x * swnc[c + 0] + x[u].y * swnc[c + 1]
                 + x[u].z * swnc[c + 2] + x[u].w * swnc[c + 3];
        }
    }

    // ---- edge MLP (64 FMAs on smem broadcasts) + sigmoid ----
    const float es = es_raw * (1.0f / (float)ROWF);
    float e = 0.0f;
    #pragma unroll
    for (int j = 0; j < 64; j++)
        e += fmaxf(es * sw1[j] + sb1[j], 0.0f) * sv[j];
    const float logit = acc + e + g_C[0];
    const float imp = (1.0f / (1.0f + expf(-logit))) * smask;
    simp[t] = imp;
    __syncthreads();

    // ---- mean (768 elems, fixed order: warp shuffle + 24-partial sum) ----
    float s = simp[t];
    #pragma unroll
    for (int o = 16; o; o >>= 1) s += __shfl_xor_sync(0xFFFFFFFFu, s, o);
    if (l == 0) wred[w] = s;
    __syncthreads();
    if (t == 0) {
        float S = 0.0f;
        #pragma unroll
        for (int k = 0; k < 24; k++) S += wred[k];
        s_mean = S * (1.0f / (float)SS);
    }
    __syncthreads();
    const float mean = s_mean;

    // ---- merged count + any(pocket): one element per thread ----
    const bool core  = d < 6.0f;
    const bool shell = (d >= 6.0f) && (d < 10.0f) && (imp > mean);
    int cnt  = (p | core | shell) ? 1 : 0;
    int anyp = p ? 1 : 0;
    #pragma unroll
    for (int o = 16; o; o >>= 1) {
        cnt  += __shfl_xor_sync(0xFFFFFFFFu, cnt, o);
        anyp |= __shfl_xor_sync(0xFFFFFFFFu, anyp, o);
    }
    if (l == 0) { wcnt[w] = cnt; wany[w] = anyp; }
    __syncthreads();

    if (t == 0) {
        int Ct = 0, A = 0;
        #pragma unroll
        for (int k = 0; k < 24; k++) { Ct += wcnt[k]; A |= wany[k]; }
        float chunk;
        if (A) {
            int ml = Ct; if (ml > 256) ml = 256;               // merged_len clamp
            chunk = fminf(fmaxf((float)ml, 64.0f), 256.0f);    // clamp(adj=64, 256)
        } else {
            chunk = fminf(fmaxf(64.0f * mean, 32.0f), 128.0f); // clip(64*imp, 32, 128)
        }
        out[b] = chunk;
    }
    // pad remaining outputs (MAX_SEQ_LEN) in parallel from block 0
    if (b == 0) {
        for (int k = BB + t; k < out_size; k += 768) out[k] = 256.0f;
    }
}

// ============================================================================
extern "C" void kernel_launch(void* const* d_in, const int* in_sizes, int n_in,
                              void* d_out, int out_size)
{
    const float* node    = (const float*)d_in[0];   // [16,768,128]
    const float* edge    = (const float*)d_in[1];   // [16,768,768,16]
    const float* seqmask = (const float*)d_in[2];   // [16,768]
    const void*  pocket  = d_in[3];                 // [16,768] dtype detected at runtime
    const float* W_node  = (const float*)d_in[4];
    const float* b_node  = (const float*)d_in[5];
    const float* W_e1    = (const float*)d_in[6];
    const float* b_e1    = (const float*)d_in[7];
    const float* W_e2    = (const float*)d_in[8];
    const float* b_e2    = (const float*)d_in[9];
    const float* W_imp   = (const float*)d_in[10];
    const float* b_imp   = (const float*)d_in[11];
    float* out = (float*)d_out;

    prep_kernel<<<26, 128>>>(pocket, W_node, b_node, W_e2, b_e2, W_imp, b_imp);

    dim3 eg(SS, BB);
    edge_kernel<<<eg, 256>>>(edge);

    final2_kernel<<<BB, 768>>>(node, seqmask, W_e1, b_e1, out, out_size);
}

// round 10
// speedup vs baseline: 1.2590x; 1.1467x over previous
#include <cuda_runtime.h>
#include <cuda_bf16.h>
#include <cstdint>

// Problem shape (fixed for this problem id)
#define BB   16
#define SS   768
#define DE   16
#define HID  128
#define BSN  (BB*SS)          // 12288 rows
#define ROWF (SS*DE)          // 12288 floats per (b,i) row
#define ROWF4 (ROWF/4)        // 3072 float4 per row

// ---- scratch (no allocations allowed) ----
__device__ float g_dist[BSN];
__device__ float g_imp[BSN];
__device__ float g_wnc[HID];
__device__ float g_v[64];
__device__ float g_C[1];
__device__ unsigned char g_mask[BSN];

// ============================================================================
// Kernel 1: prep — 26 independent blocks (R7 exact, proven).
//   blocks 0..23 : dtype-detect (redundant scan, identical result) +
//                  canonicalize a 512-element slice of the pocket mask
//   block 24     : fold w_nc = W_node @ W_imp[:32]  (ONCE)
//   block 25     : fold v = W_e2 @ W_imp[32:],  C = bias fold
// ============================================================================
__global__ void __launch_bounds__(128) prep_kernel(
                            const void* __restrict__ pocket_raw,
                            const float* __restrict__ W_node,
                            const float* __restrict__ b_node,
                            const float* __restrict__ W_e2,
                            const float* __restrict__ b_e2,
                            const float* __restrict__ W_imp,
                            const float* __restrict__ b_imp)
{
    const int blk = blockIdx.x;
    const int t = threadIdx.x;

    if (blk < 24) {
        __shared__ int s_fone, s_other;
        if (t == 0) { s_fone = 0; s_other = 0; }
        __syncthreads();
        {
            const unsigned int* w = (const unsigned int*)pocket_raw;
            unsigned int x[24];
            #pragma unroll
            for (int u = 0; u < 24; u++) x[u] = w[t + u * 128];
            int lf = 0, lo = 0;
            #pragma unroll
            for (int u = 0; u < 24; u++) {
                if (x[u] == 0x3F800000u) lf++;
                else if (x[u] != 0u && x[u] != 1u) lo++;
            }
            if (lf) atomicAdd(&s_fone, lf);
            if (lo) atomicAdd(&s_other, lo);
        }
        __syncthreads();
        // mode: 0=float32 (saw 1.0f words), 2=bool/u8 (packed bytes), 1=int32
        const int mode = (s_fone > 0) ? 0 : ((s_other > 0) ? 2 : 1);

        const int base = blk * 512;
        if (mode == 0) {
            const float* p = (const float*)pocket_raw;
            #pragma unroll
            for (int u = 0; u < 4; u++) {
                const int idx = base + t + u * 128;
                g_mask[idx] = (p[idx] != 0.0f) ? 1 : 0;
            }
        } else if (mode == 1) {
            const int* p = (const int*)pocket_raw;
            #pragma unroll
            for (int u = 0; u < 4; u++) {
                const int idx = base + t + u * 128;
                g_mask[idx] = (p[idx] != 0) ? 1 : 0;
            }
        } else {
            const unsigned char* p = (const unsigned char*)pocket_raw;
            #pragma unroll
            for (int u = 0; u < 4; u++) {
                const int idx = base + t + u * 128;
                g_mask[idx] = (p[idx] != 0) ? 1 : 0;
            }
        }
    } else if (blk == 24) {
        float s = 0.0f;
        #pragma unroll
        for (int k = 0; k < 32; k++) s += W_node[t * 32 + k] * W_imp[k];
        g_wnc[t] = s;
    } else {
        if (t < 64) {
            float s = 0.0f;
            #pragma unroll
            for (int k = 0; k < 32; k++) s += W_e2[t * 32 + k] * W_imp[32 + k];
            g_v[t] = s;
        }
        if (t == 0) {
            float c = b_imp[0];
            #pragma unroll
            for (int k = 0; k < 32; k++) c += b_node[k] * W_imp[k];
            #pragma unroll
            for (int k = 0; k < 32; k++) c += b_e2[k] * W_imp[32 + k];
            g_C[0] = c;
        }
    }
}

// ============================================================================
// Kernel 2: edge pass + importance — 604 MB stream, main loop UNCHANGED.
// Prologue: warp 0 does this row's node dot (coalesced: lane l -> float4 #l).
// Epilogue: warp 0 computes edge-MLP (2 terms/lane + shuffle), sigmoid,
// writes g_imp and g_dist. imp_kernel is thereby eliminated.
// ============================================================================
__global__ void __launch_bounds__(256) edge_kernel(const float* __restrict__ edge,
                                                   const float* __restrict__ node,
                                                   const float* __restrict__ seqmask,
                                                   const float* __restrict__ We1,
                                                   const float* __restrict__ be1)
{
    const int i = blockIdx.x;
    const int b = blockIdx.y;
    const int t = threadIdx.x;
    const int row_id = b * SS + i;

    __shared__ unsigned char sm[SS];
    __shared__ float swnc[HID], sw1[64], sb1[64], sv[64];
    for (int k = t; k < SS; k += 256) sm[k] = g_mask[b * SS + k];
    if (t < HID) swnc[t] = g_wnc[t];
    if (t >= 128 && t < 192) {
        const int j = t - 128;
        sw1[j] = We1[j]; sb1[j] = be1[j]; sv[j] = g_v[j];
    }
    __syncthreads();

    // ---- warp 0: node dot partial (coalesced; 1 float4 per lane) ----
    float nacc = 0.0f;
    if (t < 32) {
        const float4 nv = __ldg((const float4*)(node + (size_t)row_id * HID) + t);
        nacc = nv.x * swnc[t * 4 + 0] + nv.y * swnc[t * 4 + 1]
             + nv.z * swnc[t * 4 + 2] + nv.w * swnc[t * 4 + 3];
    }

    const float4* __restrict__ row =
        (const float4*)(edge + (size_t)row_id * (size_t)ROWF);

    const float INF = __int_as_float(0x7f800000);
    float sum0 = 0.0f, sum1 = 0.0f;
    float mn = INF;
    #pragma unroll
    for (int it = 0; it < ROWF4 / 256; it++) {
        const int k = t + it * 256;
        float4 v = __ldcs(row + k);
        if (it & 1) sum1 += (v.x + v.y) + (v.z + v.w);
        else        sum0 += (v.x + v.y) + (v.z + v.w);
        if ((k & 3) == 0) {                 // channel 0 of edge feature j
            const int j = k >> 2;
            const float cand = sm[j] ? v.x : INF;   // select, no branch
            mn = fminf(mn, cand);
        }
    }
    float sum = sum0 + sum1;

    // warp reduce
    #pragma unroll
    for (int o = 16; o; o >>= 1) {
        sum += __shfl_xor_sync(0xFFFFFFFFu, sum, o);
        mn   = fminf(mn, __shfl_xor_sync(0xFFFFFFFFu, mn, o));
    }
    __shared__ float ssum[8], smn[8];
    const int wid = t >> 5, lid = t & 31;
    if (lid == 0) { ssum[wid] = sum; smn[wid] = mn; }
    __syncthreads();

    // ---- epilogue: warp 0 computes importance for this row ----
    if (t < 32) {
        float S = 0.0f, M = INF;
        #pragma unroll
        for (int k = 0; k < 8; k++) { S += ssum[k]; M = fminf(M, smn[k]); }

        const float es = S * (1.0f / (float)ROWF);
        const float h0 = fmaxf(es * sw1[t]      + sb1[t],      0.0f);
        const float h1 = fmaxf(es * sw1[t + 32] + sb1[t + 32], 0.0f);
        float acc = nacc + h0 * sv[t] + h1 * sv[t + 32];
        #pragma unroll
        for (int o = 16; o; o >>= 1) acc += __shfl_xor_sync(0xFFFFFFFFu, acc, o);

        if (t == 0) {
            const float logit = acc + g_C[0];
            const float imp = 1.0f / (1.0f + expf(-logit));   // accurate exp
            g_imp[row_id]  = imp * seqmask[row_id];
            g_dist[row_id] = M;
        }
    }
}

// ============================================================================
// Kernel 3: finalize — one block per batch; shuffle reductions. R7 exact.
// ============================================================================
__global__ void __launch_bounds__(256) final_kernel(float* __restrict__ out, int out_size)
{
    const int b = blockIdx.x, t = threadIdx.x;
    const int w = t >> 5, l = t & 31;
    __shared__ float wred[8];
    __shared__ float s_mean;
    __shared__ int   wcnt[8], wany[8];

    // ---- mean of imp over the batch (deterministic fixed order) ----
    float s = 0.0f;
    #pragma unroll
    for (int it = 0; it < SS / 256; it++) s += g_imp[b * SS + t + it * 256];
    #pragma unroll
    for (int o = 16; o; o >>= 1) s += __shfl_xor_sync(0xFFFFFFFFu, s, o);
    if (l == 0) wred[w] = s;
    __syncthreads();
    if (t == 0) {
        float S = 0.0f;
        #pragma unroll
        for (int k = 0; k < 8; k++) S += wred[k];
        s_mean = S * (1.0f / (float)SS);
    }
    __syncthreads();
    const float mean = s_mean;

    // ---- merged count + any(pocket) ----
    int cnt = 0, anyp = 0;
    #pragma unroll
    for (int it = 0; it < SS / 256; it++) {
        const int idx = b * SS + t + it * 256;
        const bool p = g_mask[idx] != 0;
        const float d = g_dist[idx];
        const bool core  = d < 6.0f;
        const bool shell = (d >= 6.0f) && (d < 10.0f) && (g_imp[idx] > mean);
        cnt += (p | core | shell) ? 1 : 0;
        anyp |= p ? 1 : 0;
    }
    #pragma unroll
    for (int o = 16; o; o >>= 1) {
        cnt  += __shfl_xor_sync(0xFFFFFFFFu, cnt, o);
        anyp |= __shfl_xor_sync(0xFFFFFFFFu, anyp, o);
    }
    if (l == 0) { wcnt[w] = cnt; wany[w] = anyp; }
    __syncthreads();

    if (t == 0) {
        int C = 0, A = 0;
        #pragma unroll
        for (int k = 0; k < 8; k++) { C += wcnt[k]; A |= wany[k]; }
        float chunk;
        if (A) {
            int ml = C; if (ml > 256) ml = 256;                // merged_len clamp
            chunk = fminf(fmaxf((float)ml, 64.0f), 256.0f);    // clamp(adj=64, 256)
        } else {
            chunk = fminf(fmaxf(64.0f * mean, 32.0f), 128.0f); // clip(64*imp, 32, 128)
        }
        out[b] = chunk;
    }
    // pad remaining outputs (MAX_SEQ_LEN) in parallel from block 0
    if (b == 0) {
        for (int k = BB + t; k < out_size; k += 256) out[k] = 256.0f;
    }
}

// ============================================================================
extern "C" void kernel_launch(void* const* d_in, const int* in_sizes, int n_in,
                              void* d_out, int out_size)
{
    const float* node    = (const float*)d_in[0];   // [16,768,128]
    const float* edge    = (const float*)d_in[1];   // [16,768,768,16]
    const float* seqmask = (const float*)d_in[2];   // [16,768]
    const void*  pocket  = d_in[3];                 // [16,768] dtype detected at runtime
    const float* W_node  = (const float*)d_in[4];
    const float* b_node  = (const float*)d_in[5];
    const float* W_e1    = (const float*)d_in[6];
    const float* b_e1    = (const float*)d_in[7];
    const float* W_e2    = (const float*)d_in[8];
    const float* b_e2    = (const float*)d_in[9];
    const float* W_imp   = (const float*)d_in[10];
    const float* b_imp   = (const float*)d_in[11];
    float* out = (float*)d_out;

    prep_kernel<<<26, 128>>>(pocket, W_node, b_node, W_e2, b_e2, W_imp, b_imp);

    dim3 eg(SS, BB);
    edge_kernel<<<eg, 256>>>(edge, node, seqmask, W_e1, b_e1);

    final_kernel<<<BB, 256>>>(out, out_size);
}

// round 11
// speedup vs baseline: 1.2624x; 1.0028x over previous
#include <cuda_runtime.h>
#include <cuda_bf16.h>
#include <cstdint>

// Problem shape (fixed for this problem id)
#define BB   16
#define SS   768
#define DE   16
#define HID  128
#define BSN  (BB*SS)          // 12288 rows
#define ROWF (SS*DE)          // 12288 floats per (b,i) row
#define ROWF4 (ROWF/4)        // 3072 float4 per row

// ---- scratch (no allocations allowed) ----
__device__ float g_dist[BSN];
__device__ float g_imp[BSN];
__device__ float g_wnc[HID];
__device__ float g_v[64];
__device__ float g_C[1];
__device__ unsigned char g_mask[BSN];

// ============================================================================
// Kernel 1: prep — 26 independent blocks (proven).
//   blocks 0..23 : dtype-detect (redundant scan, identical result) +
//                  canonicalize a 512-element slice of the pocket mask
//   block 24     : fold w_nc = W_node @ W_imp[:32]  (ONCE)
//   block 25     : fold v = W_e2 @ W_imp[32:],  C = bias fold
// ============================================================================
__global__ void __launch_bounds__(128) prep_kernel(
                            const void* __restrict__ pocket_raw,
                            const float* __restrict__ W_node,
                            const float* __restrict__ b_node,
                            const float* __restrict__ W_e2,
                            const float* __restrict__ b_e2,
                            const float* __restrict__ W_imp,
                            const float* __restrict__ b_imp)
{
    const int blk = blockIdx.x;
    const int t = threadIdx.x;

    if (blk < 24) {
        __shared__ int s_fone, s_other;
        if (t == 0) { s_fone = 0; s_other = 0; }
        __syncthreads();
        {
            const unsigned int* w = (const unsigned int*)pocket_raw;
            unsigned int x[24];
            #pragma unroll
            for (int u = 0; u < 24; u++) x[u] = w[t + u * 128];
            int lf = 0, lo = 0;
            #pragma unroll
            for (int u = 0; u < 24; u++) {
                if (x[u] == 0x3F800000u) lf++;
                else if (x[u] != 0u && x[u] != 1u) lo++;
            }
            if (lf) atomicAdd(&s_fone, lf);
            if (lo) atomicAdd(&s_other, lo);
        }
        __syncthreads();
        // mode: 0=float32 (saw 1.0f words), 2=bool/u8 (packed bytes), 1=int32
        const int mode = (s_fone > 0) ? 0 : ((s_other > 0) ? 2 : 1);

        const int base = blk * 512;
        if (mode == 0) {
            const float* p = (const float*)pocket_raw;
            #pragma unroll
            for (int u = 0; u < 4; u++) {
                const int idx = base + t + u * 128;
                g_mask[idx] = (p[idx] != 0.0f) ? 1 : 0;
            }
        } else if (mode == 1) {
            const int* p = (const int*)pocket_raw;
            #pragma unroll
            for (int u = 0; u < 4; u++) {
                const int idx = base + t + u * 128;
                g_mask[idx] = (p[idx] != 0) ? 1 : 0;
            }
        } else {
            const unsigned char* p = (const unsigned char*)pocket_raw;
            #pragma unroll
            for (int u = 0; u < 4; u++) {
                const int idx = base + t + u * 128;
                g_mask[idx] = (p[idx] != 0) ? 1 : 0;
            }
        }
    } else if (blk == 24) {
        float s = 0.0f;
        #pragma unroll
        for (int k = 0; k < 32; k++) s += W_node[t * 32 + k] * W_imp[k];
        g_wnc[t] = s;
    } else {
        if (t < 64) {
            float s = 0.0f;
            #pragma unroll
            for (int k = 0; k < 32; k++) s += W_e2[t * 32 + k] * W_imp[32 + k];
            g_v[t] = s;
        }
        if (t == 0) {
            float c = b_imp[0];
            #pragma unroll
            for (int k = 0; k < 32; k++) c += b_node[k] * W_imp[k];
            #pragma unroll
            for (int k = 0; k < 32; k++) c += b_e2[k] * W_imp[32 + k];
            g_C[0] = c;
        }
    }
}

// ============================================================================
// Kernel 2: edge pass + importance — 604 MB stream (R10 exact) + PDL.
// cudaGridDependencySynchronize() before consuming prep outputs;
// cudaTriggerProgrammaticLaunchCompletion() after last global writes.
// ============================================================================
__global__ void __launch_bounds__(256) edge_kernel(const float* __restrict__ edge,
                                                   const float* __restrict__ node,
                                                   const float* __restrict__ seqmask,
                                                   const float* __restrict__ We1,
                                                   const float* __restrict__ be1)
{
    const int i = blockIdx.x;
    const int b = blockIdx.y;
    const int t = threadIdx.x;
    const int row_id = b * SS + i;

    // Wait for prep's writes (g_mask/g_wnc/g_v/g_C) to be visible.
    cudaGridDependencySynchronize();

    __shared__ unsigned char sm[SS];
    __shared__ float swnc[HID], sw1[64], sb1[64], sv[64];
    for (int k = t; k < SS; k += 256) sm[k] = g_mask[b * SS + k];
    if (t < HID) swnc[t] = g_wnc[t];
    if (t >= 128 && t < 192) {
        const int j = t - 128;
        sw1[j] = We1[j]; sb1[j] = be1[j]; sv[j] = g_v[j];
    }
    __syncthreads();

    // ---- warp 0: node dot partial (coalesced; 1 float4 per lane) ----
    float nacc = 0.0f;
    if (t < 32) {
        const float4 nv = __ldg((const float4*)(node + (size_t)row_id * HID) + t);
        nacc = nv.x * swnc[t * 4 + 0] + nv.y * swnc[t * 4 + 1]
             + nv.z * swnc[t * 4 + 2] + nv.w * swnc[t * 4 + 3];
    }

    const float4* __restrict__ row =
        (const float4*)(edge + (size_t)row_id * (size_t)ROWF);

    const float INF = __int_as_float(0x7f800000);
    float sum0 = 0.0f, sum1 = 0.0f;
    float mn = INF;
    #pragma unroll
    for (int it = 0; it < ROWF4 / 256; it++) {
        const int k = t + it * 256;
        float4 v = __ldcs(row + k);
        if (it & 1) sum1 += (v.x + v.y) + (v.z + v.w);
        else        sum0 += (v.x + v.y) + (v.z + v.w);
        if ((k & 3) == 0) {                 // channel 0 of edge feature j
            const int j = k >> 2;
            const float cand = sm[j] ? v.x : INF;   // select, no branch
            mn = fminf(mn, cand);
        }
    }
    float sum = sum0 + sum1;

    // warp reduce
    #pragma unroll
    for (int o = 16; o; o >>= 1) {
        sum += __shfl_xor_sync(0xFFFFFFFFu, sum, o);
        mn   = fminf(mn, __shfl_xor_sync(0xFFFFFFFFu, mn, o));
    }
    __shared__ float ssum[8], smn[8];
    const int wid = t >> 5, lid = t & 31;
    if (lid == 0) { ssum[wid] = sum; smn[wid] = mn; }
    __syncthreads();

    // ---- epilogue: warp 0 computes importance for this row ----
    if (t < 32) {
        float S = 0.0f, M = INF;
        #pragma unroll
        for (int k = 0; k < 8; k++) { S += ssum[k]; M = fminf(M, smn[k]); }

        const float es = S * (1.0f / (float)ROWF);
        const float h0 = fmaxf(es * sw1[t]      + sb1[t],      0.0f);
        const float h1 = fmaxf(es * sw1[t + 32] + sb1[t + 32], 0.0f);
        float acc = nacc + h0 * sv[t] + h1 * sv[t + 32];
        #pragma unroll
        for (int o = 16; o; o >>= 1) acc += __shfl_xor_sync(0xFFFFFFFFu, acc, o);

        if (t == 0) {
            const float logit = acc + g_C[0];
            const float imp = 1.0f / (1.0f + expf(-logit));   // accurate exp
            g_imp[row_id]  = imp * seqmask[row_id];
            g_dist[row_id] = M;
        }
    }
    // Let the dependent final_kernel begin its launch/setup.
    cudaTriggerProgrammaticLaunchCompletion();
}

// ============================================================================
// Kernel 3: finalize — one block per batch; shuffle reductions (R10) + PDL.
// ============================================================================
__global__ void __launch_bounds__(256) final_kernel(float* __restrict__ out, int out_size)
{
    const int b = blockIdx.x, t = threadIdx.x;
    const int w = t >> 5, l = t & 31;
    __shared__ float wred[8];
    __shared__ float s_mean;
    __shared__ int   wcnt[8], wany[8];

    // Wait for edge_kernel's g_imp/g_dist writes.
    cudaGridDependencySynchronize();

    // ---- mean of imp over the batch (deterministic fixed order) ----
    float s = 0.0f;
    #pragma unroll
    for (int it = 0; it < SS / 256; it++) s += g_imp[b * SS + t + it * 256];
    #pragma unroll
    for (int o = 16; o; o >>= 1) s += __shfl_xor_sync(0xFFFFFFFFu, s, o);
    if (l == 0) wred[w] = s;
    __syncthreads();
    if (t == 0) {
        float S = 0.0f;
        #pragma unroll
        for (int k = 0; k < 8; k++) S += wred[k];
        s_mean = S * (1.0f / (float)SS);
    }
    __syncthreads();
    const float mean = s_mean;

    // ---- merged count + any(pocket) ----
    int cnt = 0, anyp = 0;
    #pragma unroll
    for (int it = 0; it < SS / 256; it++) {
        const int idx = b * SS + t + it * 256;
        const bool p = g_mask[idx] != 0;
        const float d = g_dist[idx];
        const bool core  = d < 6.0f;
        const bool shell = (d >= 6.0f) && (d < 10.0f) && (g_imp[idx] > mean);
        cnt += (p | core | shell) ? 1 : 0;
        anyp |= p ? 1 : 0;
    }
    #pragma unroll
    for (int o = 16; o; o >>= 1) {
        cnt  += __shfl_xor_sync(0xFFFFFFFFu, cnt, o);
        anyp |= __shfl_xor_sync(0xFFFFFFFFu, anyp, o);
    }
    if (l == 0) { wcnt[w] = cnt; wany[w] = anyp; }
    __syncthreads();

    if (t == 0) {
        int C = 0, A = 0;
        #pragma unroll
        for (int k = 0; k < 8; k++) { C += wcnt[k]; A |= wany[k]; }
        float chunk;
        if (A) {
            int ml = C; if (ml > 256) ml = 256;                // merged_len clamp
            chunk = fminf(fmaxf((float)ml, 64.0f), 256.0f);    // clamp(adj=64, 256)
        } else {
            chunk = fminf(fmaxf(64.0f * mean, 32.0f), 128.0f); // clip(64*imp, 32, 128)
        }
        out[b] = chunk;
    }
    // pad remaining outputs (MAX_SEQ_LEN) in parallel from block 0
    if (b == 0) {
        for (int k = BB + t; k < out_size; k += 256) out[k] = 256.0f;
    }
}

// ============================================================================
extern "C" void kernel_launch(void* const* d_in, const int* in_sizes, int n_in,
                              void* d_out, int out_size)
{
    const float* node    = (const float*)d_in[0];   // [16,768,128]
    const float* edge    = (const float*)d_in[1];   // [16,768,768,16]
    const float* seqmask = (const float*)d_in[2];   // [16,768]
    const void*  pocket  = d_in[3];                 // [16,768] dtype detected at runtime
    const float* W_node  = (const float*)d_in[4];
    const float* b_node  = (const float*)d_in[5];
    const float* W_e1    = (const float*)d_in[6];
    const float* b_e1    = (const float*)d_in[7];
    const float* W_e2    = (const float*)d_in[8];
    const float* b_e2    = (const float*)d_in[9];
    const float* W_imp   = (const float*)d_in[10];
    const float* b_imp   = (const float*)d_in[11];
    float* out = (float*)d_out;

    // prep: normal launch
    prep_kernel<<<26, 128>>>(pocket, W_node, b_node, W_e2, b_e2, W_imp, b_imp);

    // edge: PDL — overlap launch/setup with prep's tail
    {
        cudaLaunchConfig_t cfg = {};
        cfg.gridDim  = dim3(SS, BB, 1);
        cfg.blockDim = dim3(256, 1, 1);
        cfg.stream   = 0;
        cudaLaunchAttribute attr[1];
        attr[0].id = cudaLaunchAttributeProgrammaticStreamSerialization;
        attr[0].val.programmaticStreamSerializationAllowed = 1;
        cfg.attrs = attr;
        cfg.numAttrs = 1;
        cudaLaunchKernelEx(&cfg, edge_kernel, edge, node, seqmask, W_e1, b_e1);
    }

    // final: PDL — overlap launch/setup with edge's tail
    {
        cudaLaunchConfig_t cfg = {};
        cfg.gridDim  = dim3(BB, 1, 1);
        cfg.blockDim = dim3(256, 1, 1);
        cfg.stream   = 0;
        cudaLaunchAttribute attr[1];
        attr[0].id = cudaLaunchAttributeProgrammaticStreamSerialization;
        attr[0].val.programmaticStreamSerializationAllowed = 1;
        cfg.attrs = attr;
        cfg.numAttrs = 1;
        cudaLaunchKernelEx(&cfg, final_kernel, (float*)d_out, out_size);
    }
}